// round 6
// baseline (speedup 1.0000x reference)
#include <cuda_runtime.h>
#include <cuda_bf16.h>
#include <cstdint>
#include <cstddef>

#define VOCAB 50257
#define FEAT 1024
#define MTOT 8192
#define TILE_M 128
#define TILE_N 256
#define BK 64
#define NK (FEAT / BK)                       // 16
#define NTN ((VOCAB + TILE_N - 1) / TILE_N)  // 197
#define NTM (MTOT / TILE_M)                  // 64

// ---------------- scratch (device globals; no allocations allowed) ----------
__device__ __nv_bfloat16 g_feats[(size_t)MTOT * FEAT];      // 16.8 MB
__device__ __nv_bfloat16 g_decw[(size_t)VOCAB * FEAT];      // 103 MB
__device__ float g_part[(size_t)MTOT * NTN];                // 6.5 MB

// ---------------- helpers ----------------------------------------------------
__device__ __forceinline__ uint32_t smem_u32(const void* p) {
    return (uint32_t)__cvta_generic_to_shared(p);
}

__device__ __forceinline__ void cp16(uint32_t dst, const void* src, int srcsize) {
    asm volatile("cp.async.cg.shared.global [%0],[%1],16,%2;\n"
                 :: "r"(dst), "l"(src), "r"(srcsize));
}
#define CP_COMMIT() asm volatile("cp.async.commit_group;" ::: "memory")
#define CP_WAIT(n)  asm volatile("cp.async.wait_group %0;" :: "n"(n) : "memory")

__device__ __forceinline__ void ldmx4(uint32_t* r, uint32_t addr) {
    asm volatile("ldmatrix.sync.aligned.m8n8.x4.shared.b16 {%0,%1,%2,%3}, [%4];"
                 : "=r"(r[0]), "=r"(r[1]), "=r"(r[2]), "=r"(r[3]) : "r"(addr));
}

__device__ __forceinline__ void mma16816(float* c, const uint32_t* a,
                                         uint32_t b0, uint32_t b1) {
    asm volatile(
        "mma.sync.aligned.m16n8k16.row.col.f32.bf16.bf16.f32 "
        "{%0,%1,%2,%3}, {%4,%5,%6,%7}, {%8,%9}, {%0,%1,%2,%3};"
        : "+f"(c[0]), "+f"(c[1]), "+f"(c[2]), "+f"(c[3])
        : "r"(a[0]), "r"(a[1]), "r"(a[2]), "r"(a[3]), "r"(b0), "r"(b1));
}

// ---------------- smem layout (dynamic) ---------------------------------------
// [0, 1024)     bias tile (256 f32)
// [1024, 3072)  rs: 4 x 128 f32 partial row sums
// [4096, +3*49152) 3 stages x (A 16KB | B 32KB)
// epilogue reuses [4096, ...): 8 warps x 64x33 f32 staging (67584 B)
#define STAGE_BYTES 49152
#define SM_TOTAL (4096 + 3 * STAGE_BYTES)   // 151552

// ---------------- kernel 1: dec_w fp32 -> bf16 -------------------------------
__global__ void __launch_bounds__(256) convw_kernel(const float* __restrict__ w) {
    size_t i = (size_t)blockIdx.x * 256 + threadIdx.x;  // VOCAB*FEAT/4 iterations
    float4 x = ((const float4*)w)[i];
    __nv_bfloat162 lo, hi;
    lo.x = __float2bfloat16(x.x); lo.y = __float2bfloat16(x.y);
    hi.x = __float2bfloat16(x.z); hi.y = __float2bfloat16(x.w);
    ((__nv_bfloat162*)g_decw)[2 * i]     = lo;
    ((__nv_bfloat162*)g_decw)[2 * i + 1] = hi;
}

// ---------------- kernel 2: gather + bias + L2 normalize -> bf16 --------------
__global__ void __launch_bounds__(256) feats_kernel(const int* __restrict__ tok,
                                                    const float* __restrict__ enc_w,
                                                    const float* __restrict__ enc_b) {
    __shared__ float red[8];
    __shared__ float s_inv;
    int m = blockIdx.x;
    int t = tok[m];
    float v[4];
    float ss = 0.f;
#pragma unroll
    for (int i = 0; i < 4; i++) {
        int f = threadIdx.x + i * 256;
        v[i] = enc_w[(size_t)f * VOCAB + t] + enc_b[f];
        ss += v[i] * v[i];
    }
#pragma unroll
    for (int o = 16; o; o >>= 1) ss += __shfl_xor_sync(0xffffffffu, ss, o);
    if ((threadIdx.x & 31) == 0) red[threadIdx.x >> 5] = ss;
    __syncthreads();
    if (threadIdx.x == 0) {
        float tot = 0.f;
#pragma unroll
        for (int i = 0; i < 8; i++) tot += red[i];
        s_inv = 1.f / fmaxf(sqrtf(tot), 1e-12f);
    }
    __syncthreads();
    float inv = s_inv;
#pragma unroll
    for (int i = 0; i < 4; i++) {
        int f = threadIdx.x + i * 256;
        g_feats[(size_t)m * FEAT + f] = __float2bfloat16(v[i] * inv);
    }
}

// ---------------- kernel 3: HMMA GEMM + bias + partial sumexp -----------------
// grid: (NTM, NTN)  -- mtile fastest so a wave shares B tiles via L2
__global__ void __launch_bounds__(256, 1) gemm_ls_kernel(const float* __restrict__ dec_b,
                                                         float* __restrict__ out) {
    extern __shared__ char dsm[];
    const int tid = threadIdx.x;
    const int lane = tid & 31, w = tid >> 5;
    const int wm = w >> 2, wn = w & 3;     // warp grid 2(M) x 4(N); warp tile 64x64
    const int m0 = blockIdx.x * TILE_M;
    const int n0 = blockIdx.y * TILE_N;

    float* bias_s = (float*)dsm;
    float* rs = (float*)(dsm + 1024);
    uint32_t sb = smem_u32(dsm);

    {
        int v = n0 + tid;
        bias_s[tid] = (v < VOCAB) ? dec_b[v] : 0.f;
    }

    auto load_stage = [&](int kk, int s) {
        uint32_t abase = sb + 4096 + s * STAGE_BYTES;
        uint32_t bbase = abase + 16384;
        const __nv_bfloat16* Ag = g_feats + (size_t)m0 * FEAT + kk * BK;
        const __nv_bfloat16* Bg = g_decw + (size_t)n0 * FEAT + kk * BK;
#pragma unroll
        for (int i = 0; i < 4; i++) {           // A: 128 rows x 128B
            int c = tid + i * 256;
            int r = c >> 3, j = c & 7;
            uint32_t off = (uint32_t)(r * 128 + j * 16);
            cp16(abase + (off ^ ((r & 7) * 16)), Ag + (size_t)r * FEAT + j * 8, 16);
        }
#pragma unroll
        for (int i = 0; i < 8; i++) {           // B: 256 rows x 128B
            int c = tid + i * 256;
            int r = c >> 3, j = c & 7;
            uint32_t off = (uint32_t)(r * 128 + j * 16);
            int ok = (n0 + r) < VOCAB;
            const void* src = Bg + (size_t)(ok ? r : 0) * FEAT + j * 8;
            cp16(bbase + (off ^ ((r & 7) * 16)), src, ok ? 16 : 0);
        }
    };

    float acc[4][8][4];
#pragma unroll
    for (int a = 0; a < 4; a++)
#pragma unroll
        for (int b = 0; b < 8; b++)
#pragma unroll
            for (int c = 0; c < 4; c++) acc[a][b][c] = 0.f;

    load_stage(0, 0); CP_COMMIT();
    load_stage(1, 1); CP_COMMIT();

    const int r15 = lane & 15;
    const int cbl = (lane >> 4) * 16;

    for (int k = 0; k < NK; k++) {
        const int buf = k % 3;
        CP_WAIT(1);            // stage k resident
        __syncthreads();       // all warps done with the buffer being overwritten
        if (k + 2 < NK) load_stage(k + 2, (k + 2) % 3);
        CP_COMMIT();           // unconditional: keeps group accounting aligned

        uint32_t abase = sb + 4096 + buf * STAGE_BYTES;
        uint32_t bbase = abase + 16384;
#pragma unroll
        for (int ks = 0; ks < 4; ks++) {       // 4 x k16 per BK=64
            uint32_t af[4][4], bf[4][4];
#pragma unroll
            for (int mc = 0; mc < 4; mc++) {
                int row = wm * 64 + mc * 16 + r15;
                uint32_t off = (uint32_t)(row * 128 + ks * 32 + cbl);
                ldmx4(af[mc], abase + (off ^ ((row & 7) * 16)));
            }
#pragma unroll
            for (int nc = 0; nc < 4; nc++) {
                int row = wn * 64 + nc * 16 + r15;
                uint32_t off = (uint32_t)(row * 128 + ks * 32 + cbl);
                ldmx4(bf[nc], bbase + (off ^ ((row & 7) * 16)));
            }
#pragma unroll
            for (int mc = 0; mc < 4; mc++)
#pragma unroll
                for (int n8 = 0; n8 < 8; n8++)
                    mma16816(acc[mc][n8], af[mc],
                             bf[n8 >> 1][n8 & 1], bf[n8 >> 1][(n8 & 1) + 2]);
        }
    }
    __syncthreads();   // stage buffers free for epilogue staging

    // ---------------- epilogue ----------------
    const int g = lane >> 2, tig = lane & 3;
    float* ws = (float*)(dsm + 4096) + w * (64 * 33);

    float se[4][2];
#pragma unroll
    for (int mi = 0; mi < 4; mi++) { se[mi][0] = 0.f; se[mi][1] = 0.f; }

#pragma unroll
    for (int p = 0; p < 2; p++) {              // two 32-col halves of the 64-col warp tile
#pragma unroll
        for (int mi = 0; mi < 4; mi++) {
#pragma unroll
            for (int nn = 0; nn < 4; nn++) {
                int n8 = p * 4 + nn;
                int cl = wn * 64 + n8 * 8 + tig * 2;
                float b0 = bias_s[cl], b1 = bias_s[cl + 1];
                bool v0 = (n0 + cl) < VOCAB, v1 = (n0 + cl + 1) < VOCAB;
                float x0 = acc[mi][n8][0] + b0;
                float x1 = acc[mi][n8][1] + b1;
                float x2 = acc[mi][n8][2] + b0;
                float x3 = acc[mi][n8][3] + b1;
                if (v0) se[mi][0] += __expf(x0);
                if (v1) se[mi][0] += __expf(x1);
                if (v0) se[mi][1] += __expf(x2);
                if (v1) se[mi][1] += __expf(x3);
                int c0 = nn * 8 + tig * 2;
                int row0 = mi * 16 + g, row1 = row0 + 8;
                ws[row0 * 33 + c0]     = x0;
                ws[row0 * 33 + c0 + 1] = x1;
                ws[row1 * 33 + c0]     = x2;
                ws[row1 * 33 + c0 + 1] = x3;
            }
        }
        __syncwarp();
        {   // coalesced stores: lane = column
            const int gmrow = m0 + wm * 64;
            const int v = n0 + wn * 64 + p * 32 + lane;
            if (v < VOCAB) {
#pragma unroll 4
                for (int r = 0; r < 64; r++)
                    out[(size_t)(gmrow + r) * VOCAB + v] = ws[r * 33 + lane];
            }
        }
        __syncwarp();
    }

    // deterministic quad reduce (lanes tig=0..3 share the same M rows)
#pragma unroll
    for (int mi = 0; mi < 4; mi++)
#pragma unroll
        for (int r8 = 0; r8 < 2; r8++) {
            float s = se[mi][r8];
            s += __shfl_xor_sync(0xffffffffu, s, 1);
            s += __shfl_xor_sync(0xffffffffu, s, 2);
            if (tig == 0)
                rs[wn * 128 + wm * 64 + mi * 16 + g + r8 * 8] = s;
        }

    __syncthreads();
    if (tid < 128) {
        float t = rs[tid] + rs[128 + tid] + rs[256 + tid] + rs[384 + tid];
        g_part[(size_t)(m0 + tid) * NTN + blockIdx.y] = t;
    }
}

// ---------------- kernel 4: row LSE + subtract (alignment-safe float4) --------
__global__ void __launch_bounds__(256) lse_kernel(float* __restrict__ out) {
    __shared__ float red[8];
    __shared__ float s_lse;
    int m = blockIdx.x;
    float s = 0.f;
    if (threadIdx.x < NTN) s = g_part[(size_t)m * NTN + threadIdx.x];
#pragma unroll
    for (int o = 16; o; o >>= 1) s += __shfl_xor_sync(0xffffffffu, s, o);
    if ((threadIdx.x & 31) == 0) red[threadIdx.x >> 5] = s;
    __syncthreads();
    if (threadIdx.x == 0) {
        float tot = 0.f;
#pragma unroll
        for (int i = 0; i < 8; i++) tot += red[i];
        s_lse = logf(tot);
    }
    __syncthreads();
    float lse = s_lse;
    float* row = out + (size_t)m * VOCAB;

    // row base is only 4B-aligned in general (VOCAB % 4 == 1): do a scalar
    // prologue until 16B alignment, vectorize the body, scalar tail.
    int pre = (int)(((16u - ((uint32_t)(uintptr_t)row & 15u)) & 15u) >> 2);
    if (pre > (int)VOCAB) pre = VOCAB;
    if (threadIdx.x < pre) row[threadIdx.x] -= lse;

    float4* row4 = (float4*)(row + pre);
    int nv4 = (VOCAB - pre) >> 2;
    for (int i = threadIdx.x; i < nv4; i += 256) {
        float4 x = row4[i];
        x.x -= lse; x.y -= lse; x.z -= lse; x.w -= lse;
        row4[i] = x;
    }
    int done = pre + nv4 * 4;
    int rem = VOCAB - done;
    if ((int)threadIdx.x < rem) row[done + threadIdx.x] -= lse;
}

// ---------------- launch -------------------------------------------------------
extern "C" void kernel_launch(void* const* d_in, const int* in_sizes, int n_in,
                              void* d_out, int out_size) {
    const int* tok     = (const int*)d_in[0];
    const float* enc_w = (const float*)d_in[1];
    const float* enc_b = (const float*)d_in[2];
    const float* dec_w = (const float*)d_in[3];
    const float* dec_b = (const float*)d_in[4];
    float* out = (float*)d_out;

    convw_kernel<<<VOCAB, 256>>>(dec_w);
    feats_kernel<<<MTOT, 256>>>(tok, enc_w, enc_b);

    cudaFuncSetAttribute(gemm_ls_kernel,
                         cudaFuncAttributeMaxDynamicSharedMemorySize, SM_TOTAL);
    dim3 grid(NTM, NTN);   // mtile fastest -> B tiles shared across the wave in L2
    gemm_ls_kernel<<<grid, 256, SM_TOTAL>>>(dec_b, out);

    lse_kernel<<<MTOT, 256>>>(out);
}

// round 7
// speedup vs baseline: 1.1382x; 1.1382x over previous
#include <cuda_runtime.h>
#include <cuda_bf16.h>
#include <cstdint>
#include <cstddef>

#define VOCAB 50257
#define FEAT 1024
#define MTOT 8192
#define TILE_M 128
#define TILE_N 128
#define BK 64
#define NK (FEAT / BK)                       // 16
#define NTN ((VOCAB + TILE_N - 1) / TILE_N)  // 393
#define NTM (MTOT / TILE_M)                  // 64

// ---------------- scratch (device globals; no allocations allowed) ----------
__device__ __nv_bfloat16 g_feats[(size_t)MTOT * FEAT];      // 16.8 MB
__device__ __nv_bfloat16 g_decw[(size_t)VOCAB * FEAT];      // 103 MB
__device__ float g_part[(size_t)MTOT * NTN];                // 12.9 MB

// ---------------- helpers ----------------------------------------------------
__device__ __forceinline__ uint32_t smem_u32(const void* p) {
    return (uint32_t)__cvta_generic_to_shared(p);
}

__device__ __forceinline__ void cp16(uint32_t dst, const void* src, int srcsize) {
    asm volatile("cp.async.cg.shared.global [%0],[%1],16,%2;\n"
                 :: "r"(dst), "l"(src), "r"(srcsize));
}
#define CP_COMMIT() asm volatile("cp.async.commit_group;" ::: "memory")
#define CP_WAIT(n)  asm volatile("cp.async.wait_group %0;" :: "n"(n) : "memory")

__device__ __forceinline__ void ldmx4(uint32_t* r, uint32_t addr) {
    asm volatile("ldmatrix.sync.aligned.m8n8.x4.shared.b16 {%0,%1,%2,%3}, [%4];"
                 : "=r"(r[0]), "=r"(r[1]), "=r"(r[2]), "=r"(r[3]) : "r"(addr));
}

__device__ __forceinline__ void mma16816(float* c, const uint32_t* a,
                                         uint32_t b0, uint32_t b1) {
    asm volatile(
        "mma.sync.aligned.m16n8k16.row.col.f32.bf16.bf16.f32 "
        "{%0,%1,%2,%3}, {%4,%5,%6,%7}, {%8,%9}, {%0,%1,%2,%3};"
        : "+f"(c[0]), "+f"(c[1]), "+f"(c[2]), "+f"(c[3])
        : "r"(a[0]), "r"(a[1]), "r"(a[2]), "r"(a[3]), "r"(b0), "r"(b1));
}

// ---------------- smem layout (dynamic, per CTA 102400 B -> 2 CTAs/SM) -------
// [0, 512)      bias tile (128 f32)
// [512, 1536)   rs: 2 x 128 f32 partial row sums
// [4096, +3*32768) 3 stages x (A 16KB | B 16KB)
// epilogue reuses [4096, ...): 4 warps x 64x33 f32 staging (33792 B)
#define STAGE_BYTES 32768
#define SM_TOTAL (4096 + 3 * STAGE_BYTES)   // 102400

// ---------------- kernel 1: dec_w fp32 -> bf16 -------------------------------
__global__ void __launch_bounds__(256) convw_kernel(const float* __restrict__ w) {
    size_t i = (size_t)blockIdx.x * 256 + threadIdx.x;
    float4 x = ((const float4*)w)[i];
    __nv_bfloat162 lo, hi;
    lo.x = __float2bfloat16(x.x); lo.y = __float2bfloat16(x.y);
    hi.x = __float2bfloat16(x.z); hi.y = __float2bfloat16(x.w);
    ((__nv_bfloat162*)g_decw)[2 * i]     = lo;
    ((__nv_bfloat162*)g_decw)[2 * i + 1] = hi;
}

// ---------------- kernel 2: gather + bias + L2 normalize -> bf16 --------------
__global__ void __launch_bounds__(256) feats_kernel(const int* __restrict__ tok,
                                                    const float* __restrict__ enc_w,
                                                    const float* __restrict__ enc_b) {
    __shared__ float red[8];
    __shared__ float s_inv;
    int m = blockIdx.x;
    int t = tok[m];
    float v[4];
    float ss = 0.f;
#pragma unroll
    for (int i = 0; i < 4; i++) {
        int f = threadIdx.x + i * 256;
        v[i] = enc_w[(size_t)f * VOCAB + t] + enc_b[f];
        ss += v[i] * v[i];
    }
#pragma unroll
    for (int o = 16; o; o >>= 1) ss += __shfl_xor_sync(0xffffffffu, ss, o);
    if ((threadIdx.x & 31) == 0) red[threadIdx.x >> 5] = ss;
    __syncthreads();
    if (threadIdx.x == 0) {
        float tot = 0.f;
#pragma unroll
        for (int i = 0; i < 8; i++) tot += red[i];
        s_inv = 1.f / fmaxf(sqrtf(tot), 1e-12f);
    }
    __syncthreads();
    float inv = s_inv;
#pragma unroll
    for (int i = 0; i < 4; i++) {
        int f = threadIdx.x + i * 256;
        g_feats[(size_t)m * FEAT + f] = __float2bfloat16(v[i] * inv);
    }
}

// ---------------- kernel 3: HMMA GEMM + bias + partial sumexp -----------------
// 128 threads (4 warps, 2x2 warp grid, warp tile 64x64); 2 CTAs/SM.
// grid: (NTM, NTN) -- mtile fastest so a wave shares B tiles via L2
__global__ void __launch_bounds__(128, 2) gemm_ls_kernel(const float* __restrict__ dec_b,
                                                         float* __restrict__ out) {
    extern __shared__ char dsm[];
    const int tid = threadIdx.x;
    const int lane = tid & 31, w = tid >> 5;
    const int wm = w >> 1, wn = w & 1;     // warp grid 2(M) x 2(N)
    const int m0 = blockIdx.x * TILE_M;
    const int n0 = blockIdx.y * TILE_N;

    float* bias_s = (float*)dsm;
    float* rs = (float*)(dsm + 512);
    uint32_t sb = smem_u32(dsm);

    {
        int v = n0 + tid;
        bias_s[tid] = (v < VOCAB) ? dec_b[v] : 0.f;
    }

    auto load_stage = [&](int kk, int s) {
        uint32_t abase = sb + 4096 + s * STAGE_BYTES;
        uint32_t bbase = abase + 16384;
        const __nv_bfloat16* Ag = g_feats + (size_t)m0 * FEAT + kk * BK;
        const __nv_bfloat16* Bg = g_decw + (size_t)n0 * FEAT + kk * BK;
#pragma unroll
        for (int i = 0; i < 8; i++) {           // A: 128 rows x 128B
            int c = tid + i * 128;
            int r = c >> 3, j = c & 7;
            uint32_t off = (uint32_t)(r * 128 + j * 16);
            cp16(abase + (off ^ ((r & 7) * 16)), Ag + (size_t)r * FEAT + j * 8, 16);
        }
#pragma unroll
        for (int i = 0; i < 8; i++) {           // B: 128 rows x 128B
            int c = tid + i * 128;
            int r = c >> 3, j = c & 7;
            uint32_t off = (uint32_t)(r * 128 + j * 16);
            int ok = (n0 + r) < VOCAB;
            const void* src = Bg + (size_t)(ok ? r : 0) * FEAT + j * 8;
            cp16(bbase + (off ^ ((r & 7) * 16)), src, ok ? 16 : 0);
        }
    };

    float acc[4][8][4];
#pragma unroll
    for (int a = 0; a < 4; a++)
#pragma unroll
        for (int b = 0; b < 8; b++)
#pragma unroll
            for (int c = 0; c < 4; c++) acc[a][b][c] = 0.f;

    load_stage(0, 0); CP_COMMIT();
    load_stage(1, 1); CP_COMMIT();

    const int r15 = lane & 15;
    const int cbl = (lane >> 4) * 16;

    for (int k = 0; k < NK; k++) {
        const int buf = k % 3;
        CP_WAIT(1);            // stage k resident
        __syncthreads();       // all warps done with the buffer being overwritten
        if (k + 2 < NK) load_stage(k + 2, (k + 2) % 3);
        CP_COMMIT();

        uint32_t abase = sb + 4096 + buf * STAGE_BYTES;
        uint32_t bbase = abase + 16384;
#pragma unroll
        for (int ks = 0; ks < 4; ks++) {       // 4 x k16 per BK=64
            uint32_t af[4][4], bf[4][4];
#pragma unroll
            for (int mc = 0; mc < 4; mc++) {
                int row = wm * 64 + mc * 16 + r15;
                uint32_t off = (uint32_t)(row * 128 + ks * 32 + cbl);
                ldmx4(af[mc], abase + (off ^ ((row & 7) * 16)));
            }
#pragma unroll
            for (int nc = 0; nc < 4; nc++) {
                int row = wn * 64 + nc * 16 + r15;
                uint32_t off = (uint32_t)(row * 128 + ks * 32 + cbl);
                ldmx4(bf[nc], bbase + (off ^ ((row & 7) * 16)));
            }
#pragma unroll
            for (int mc = 0; mc < 4; mc++)
#pragma unroll
                for (int n8 = 0; n8 < 8; n8++)
                    mma16816(acc[mc][n8], af[mc],
                             bf[n8 >> 1][n8 & 1], bf[n8 >> 1][(n8 & 1) + 2]);
        }
    }
    __syncthreads();   // stage buffers free for epilogue staging

    // ---------------- epilogue ----------------
    const int g = lane >> 2, tig = lane & 3;
    float* ws = (float*)(dsm + 4096) + w * (64 * 33);

    float se[4][2];
#pragma unroll
    for (int mi = 0; mi < 4; mi++) { se[mi][0] = 0.f; se[mi][1] = 0.f; }

#pragma unroll
    for (int p = 0; p < 2; p++) {              // two 32-col halves of the 64-col warp tile
#pragma unroll
        for (int mi = 0; mi < 4; mi++) {
#pragma unroll
            for (int nn = 0; nn < 4; nn++) {
                int n8 = p * 4 + nn;
                int cl = wn * 64 + n8 * 8 + tig * 2;
                float b0 = bias_s[cl], b1 = bias_s[cl + 1];
                bool v0 = (n0 + cl) < VOCAB, v1 = (n0 + cl + 1) < VOCAB;
                float x0 = acc[mi][n8][0] + b0;
                float x1 = acc[mi][n8][1] + b1;
                float x2 = acc[mi][n8][2] + b0;
                float x3 = acc[mi][n8][3] + b1;
                if (v0) se[mi][0] += __expf(x0);
                if (v1) se[mi][0] += __expf(x1);
                if (v0) se[mi][1] += __expf(x2);
                if (v1) se[mi][1] += __expf(x3);
                int c0 = nn * 8 + tig * 2;
                int row0 = mi * 16 + g, row1 = row0 + 8;
                ws[row0 * 33 + c0]     = x0;
                ws[row0 * 33 + c0 + 1] = x1;
                ws[row1 * 33 + c0]     = x2;
                ws[row1 * 33 + c0 + 1] = x3;
            }
        }
        __syncwarp();
        {   // coalesced stores: lane = column
            const int gmrow = m0 + wm * 64;
            const int v = n0 + wn * 64 + p * 32 + lane;
            if (v < VOCAB) {
#pragma unroll 4
                for (int r = 0; r < 64; r++)
                    out[(size_t)(gmrow + r) * VOCAB + v] = ws[r * 33 + lane];
            }
        }
        __syncwarp();
    }

    // deterministic quad reduce (lanes tig=0..3 share the same M rows)
#pragma unroll
    for (int mi = 0; mi < 4; mi++)
#pragma unroll
        for (int r8 = 0; r8 < 2; r8++) {
            float s = se[mi][r8];
            s += __shfl_xor_sync(0xffffffffu, s, 1);
            s += __shfl_xor_sync(0xffffffffu, s, 2);
            if (tig == 0)
                rs[wn * 128 + wm * 64 + mi * 16 + g + r8 * 8] = s;
        }

    __syncthreads();
    if (tid < 128) {
        float t = rs[tid] + rs[128 + tid];
        g_part[(size_t)(m0 + tid) * NTN + blockIdx.y] = t;
    }
}

// ---------------- kernel 4: row LSE + subtract (alignment-safe float4) --------
__global__ void __launch_bounds__(256) lse_kernel(float* __restrict__ out) {
    __shared__ float red[8];
    __shared__ float s_lse;
    int m = blockIdx.x;
    float s = 0.f;
    for (int i = threadIdx.x; i < NTN; i += 256)
        s += g_part[(size_t)m * NTN + i];
#pragma unroll
    for (int o = 16; o; o >>= 1) s += __shfl_xor_sync(0xffffffffu, s, o);
    if ((threadIdx.x & 31) == 0) red[threadIdx.x >> 5] = s;
    __syncthreads();
    if (threadIdx.x == 0) {
        float tot = 0.f;
#pragma unroll
        for (int i = 0; i < 8; i++) tot += red[i];
        s_lse = logf(tot);
    }
    __syncthreads();
    float lse = s_lse;
    float* row = out + (size_t)m * VOCAB;

    int pre = (int)(((16u - ((uint32_t)(uintptr_t)row & 15u)) & 15u) >> 2);
    if (pre > (int)VOCAB) pre = VOCAB;
    if (threadIdx.x < pre) row[threadIdx.x] -= lse;

    float4* row4 = (float4*)(row + pre);
    int nv4 = (VOCAB - pre) >> 2;
    for (int i = threadIdx.x; i < nv4; i += 256) {
        float4 x = row4[i];
        x.x -= lse; x.y -= lse; x.z -= lse; x.w -= lse;
        row4[i] = x;
    }
    int done = pre + nv4 * 4;
    int rem = VOCAB - done;
    if ((int)threadIdx.x < rem) row[done + threadIdx.x] -= lse;
}

// ---------------- launch -------------------------------------------------------
extern "C" void kernel_launch(void* const* d_in, const int* in_sizes, int n_in,
                              void* d_out, int out_size) {
    const int* tok     = (const int*)d_in[0];
    const float* enc_w = (const float*)d_in[1];
    const float* enc_b = (const float*)d_in[2];
    const float* dec_w = (const float*)d_in[3];
    const float* dec_b = (const float*)d_in[4];
    float* out = (float*)d_out;

    convw_kernel<<<VOCAB, 256>>>(dec_w);
    feats_kernel<<<MTOT, 256>>>(tok, enc_w, enc_b);

    cudaFuncSetAttribute(gemm_ls_kernel,
                         cudaFuncAttributeMaxDynamicSharedMemorySize, SM_TOTAL);
    dim3 grid(NTM, NTN);   // mtile fastest -> B tiles shared across the wave in L2
    gemm_ls_kernel<<<grid, 128, SM_TOTAL>>>(dec_b, out);

    lse_kernel<<<MTOT, 256>>>(out);
}